// round 6
// baseline (speedup 1.0000x reference)
#include <cuda_runtime.h>
#include <cstdint>

#define HH 256
#define WW 256
#define NUM_CURVES 256
#define GPER 64                            /* 2 beziers * 32 samples */
#define NGAUSS (NUM_CURVES*GPER)           /* 16384 */
#define LOG2E 1.4426950408889634f
#define NTILE 1024                         /* 32 x 32 tiles of 8x8 px */
#define MASKW (NGAUSS/32)                  /* 512 words per tile */
#define CAP 512                            /* staged survivors per chunk */
#define CUT 14.0f                          /* cutoff: a >= exp(-14) ~ 8.3e-7 */

// ---- static scratch ----
__device__ float4   d_gA[NGAUSS];            // mx, my, c0p, c1p
__device__ float4   d_gB[NGAUSS];            // c2p, log2(alpha), cr, cg
__device__ float    d_gCb[NGAUSS];           // cb
__device__ uint32_t d_mask[NTILE*MASKW];     // per-tile visibility bitmask (slot-ordered)

// ---------------------------------------------------------------------------
// K1 (fused prep + bezier + mask scatter): 128 blocks x 128 threads,
// 2 curves per block.
// ---------------------------------------------------------------------------
__global__ void __launch_bounds__(128)
k_build(const float* __restrict__ ctrl,
        const float* __restrict__ fdc,
        const float* __restrict__ chol,
        const float* __restrict__ opac,
        const float* __restrict__ depth)
{
    __shared__ float  sd[NUM_CURVES];
    __shared__ int    srank[2];
    __shared__ float4 sConic[2];
    __shared__ float4 sColEx[2];
    __shared__ float  sEy[2];

    int t   = threadIdx.x;
    int grp = t >> 6;              // 0/1
    int li  = t & 63;
    int ci  = blockIdx.x * 2 + grp;

    sd[t]       = depth[t];
    sd[t + 128] = depth[t + 128];
    if (t < 2) srank[t] = 0;
    __syncthreads();

    {   // stable rank of curve ci: 64 threads x 4 comparisons
        float d = sd[ci];
        int partial = 0;
        #pragma unroll
        for (int jj = 0; jj < 4; ++jj) {
            int j = li * 4 + jj;
            float dj = sd[j];
            partial += (dj < d) || (dj == d && j < ci);
        }
        partial += __shfl_xor_sync(0xffffffffu, partial, 16);
        partial += __shfl_xor_sync(0xffffffffu, partial, 8);
        partial += __shfl_xor_sync(0xffffffffu, partial, 4);
        partial += __shfl_xor_sync(0xffffffffu, partial, 2);
        partial += __shfl_xor_sync(0xffffffffu, partial, 1);
        if ((t & 31) == 0) atomicAdd(&srank[grp], partial);
    }

    if (t < 2) {
        int c = blockIdx.x * 2 + t;
        float c0 = chol[3*c+0] + 0.5f;
        float c1 = chol[3*c+1];
        float c2 = chol[3*c+2] + 0.5f;
        float s00 = c0*c0;
        float s01 = c0*c1;
        float s11 = c1*c1 + c2*c2;
        float inv = 1.0f / (s00*s11 - s01*s01);
        float A =  s11*inv;
        float B = -s01*inv;
        float C =  s00*inv;

        float al  = 1.0f / (1.0f + expf(-opac[c]));
        float l2a = log2f(al);
        float Q = fmaxf(2.0f * (CUT + logf(al)), 0.0f);
        float ex = sqrtf(Q * s00);
        float ey = sqrtf(Q * s11);

        sConic[t] = make_float4(-0.5f*LOG2E*A, -LOG2E*B, -0.5f*LOG2E*C, l2a);
        sColEx[t] = make_float4(1.0f/(1.0f+expf(-fdc[3*c+0])),
                                1.0f/(1.0f+expf(-fdc[3*c+1])),
                                1.0f/(1.0f+expf(-fdc[3*c+2])), ex);
        sEy[t] = ey;
    }
    __syncthreads();

    // bezier point for this thread's gaussian
    int k = li >> 5;
    int s = li & 31;
    float tt = 0.007f + (float)s * (0.986f / 31.0f);
    float u  = 1.0f - tt;
    float t2 = tt*tt, t3 = t2*tt, t4 = t2*t2, t5 = t4*tt;
    float u2 = u*u,   u3 = u2*u,  u4 = u2*u2, u5 = u4*u;
    float w0 = u5, w1 = 5.0f*tt*u4, w2 = 10.0f*t2*u3;
    float w3 = 10.0f*t3*u2, w4 = 5.0f*t4*u, w5 = t5;

    const float* cb_ = ctrl + ci * 20;
    int i0 = k*5;
    int a0=i0, a1=i0+1, a2=i0+2, a3=i0+3, a4=i0+4, a5=(i0+5)%10;
    float px = w0*cb_[a0*2]   + w1*cb_[a1*2]   + w2*cb_[a2*2]
             + w3*cb_[a3*2]   + w4*cb_[a4*2]   + w5*cb_[a5*2];
    float py = w0*cb_[a0*2+1] + w1*cb_[a1*2+1] + w2*cb_[a2*2+1]
             + w3*cb_[a3*2+1] + w4*cb_[a4*2+1] + w5*cb_[a5*2+1];
    float mx = (tanhf(px)*0.5f + 0.5f) * (float)WW;
    float my = (tanhf(py)*0.5f + 0.5f) * (float)HH;

    float4 cc = sConic[grp];
    float4 ce = sColEx[grp];
    float  ey = sEy[grp];
    int slot  = srank[grp] * 64 + li;

    d_gA[slot]  = make_float4(mx, my, cc.x, cc.y);
    d_gB[slot]  = make_float4(cc.z, cc.w, ce.x, ce.y);
    d_gCb[slot] = ce.z;

    // scatter visibility bit into 8x8-px tile masks (bit index = depth slot)
    float ex = ce.w;
    int xlo = max(0,  (int)ceilf ((mx - ex - 8.0f) * 0.125f - 1e-4f));
    int xhi = min(31, (int)floorf((mx + ex)        * 0.125f + 1e-4f));
    int ylo = max(0,  (int)ceilf ((my - ey - 8.0f) * 0.125f - 1e-4f));
    int yhi = min(31, (int)floorf((my + ey)        * 0.125f + 1e-4f));
    if (xlo <= xhi && ylo <= yhi) {
        uint32_t bit  = 1u << (slot & 31);
        int      word = slot >> 5;
        for (int ty = ylo; ty <= yhi; ++ty)
            for (int tx = xlo; tx <= xhi; ++tx)
                atomicOr(&d_mask[(ty*32 + tx)*MASKW + word], bit);
    }
}

// ---------------------------------------------------------------------------
// K2: per-tile compositing. 1024 single-warp blocks (8x8 px tile),
// 32 threads, 2 pixels each (same x, rows r and r+4).
// ---------------------------------------------------------------------------
__global__ void __launch_bounds__(32)
k_render(const float* __restrict__ bgp, float* __restrict__ out)
{
    __shared__ float4 shA[CAP];
    __shared__ float4 shB[CAP];
    __shared__ float  shCb[CAP];

    int t    = threadIdx.x;        // 0..31
    int tile = blockIdx.x;
    int tx8  = tile & 31;
    int ty8  = tile >> 5;
    int col  = t & 7;
    int row  = t >> 3;             // 0..3; second pixel at row+4
    float px  = (float)(tx8*8 + col) + 0.5f;
    float py0 = (float)(ty8*8 + row) + 0.5f;
    float py1 = py0 + 4.0f;

    // this thread owns mask words 16t..16t+15 (slots 512t..512t+511)
    const uint32_t* mw = d_mask + (size_t)tile*MASKW + t*16;
    uint4 m[4];
    m[0] = *(const uint4*)(mw);
    m[1] = *(const uint4*)(mw + 4);
    m[2] = *(const uint4*)(mw + 8);
    m[3] = *(const uint4*)(mw + 12);
    const uint32_t* ms = (const uint32_t*)m;
    int c = 0;
    #pragma unroll
    for (int w = 0; w < 16; ++w) c += __popc(ms[w]);

    // warp exclusive scan
    int incl = c;
    #pragma unroll
    for (int d = 1; d < 32; d <<= 1) {
        int v = __shfl_up_sync(0xffffffffu, incl, d);
        if (t >= d) incl += v;
    }
    int total = __shfl_sync(0xffffffffu, incl, 31);
    int off   = incl - c;

    float T0 = 1.0f, cr0 = 0.0f, cg0 = 0.0f, cb0 = 0.0f;
    float T1 = 1.0f, cr1 = 0.0f, cg1 = 0.0f, cb1 = 0.0f;

    for (int base = 0; base < total; base += CAP) {
        if (base > 0 &&
            __all_sync(0xffffffffu, (T0 < 1e-4f) & (T1 < 1e-4f))) break;
        int lim = min(base + CAP, total);

        // gather my survivors that fall in [base, lim)
        if (off < lim && off + c > base) {
            int o = off;
            #pragma unroll
            for (int w = 0; w < 16; ++w) {
                uint32_t mm = ms[w];
                int sb = t*512 + w*32;
                while (mm) {
                    int b = __ffs(mm) - 1;
                    mm &= mm - 1;
                    if (o >= base && o < lim) {
                        int j = o - base;
                        int slot = sb + b;
                        shA[j]  = d_gA[slot];
                        shB[j]  = d_gB[slot];
                        shCb[j] = d_gCb[slot];
                    }
                    ++o;
                }
            }
        }
        __syncwarp();

        int n = lim - base;
        int i = 0;
        while (i < n) {
            int ie = min(i + 64, n);
            if ((T0 >= 1e-4f) | (T1 >= 1e-4f)) {
                for (; i < ie; ++i) {
                    float4 A = shA[i];
                    float4 B = shB[i];
                    float dx  = px  - A.x;
                    float dy0 = py0 - A.y;
                    float dy1 = py1 - A.y;
                    float bse = fmaf(A.z, dx*dx, B.y);   // Az*dx^2 + log2(a)
                    float awd = A.w * dx;                 // Aw*dx
                    float e0 = fmaf(dy0, fmaf(B.x, dy0, awd), bse);
                    float e1 = fmaf(dy1, fmaf(B.x, dy1, awd), bse);
                    float a0, a1;
                    asm("ex2.approx.f32 %0, %1;" : "=f"(a0) : "f"(e0));
                    asm("ex2.approx.f32 %0, %1;" : "=f"(a1) : "f"(e1));
                    float w0 = a0 * T0;
                    float w1 = a1 * T1;
                    float cbv = shCb[i];
                    cr0 = fmaf(w0, B.z, cr0);  cr1 = fmaf(w1, B.z, cr1);
                    cg0 = fmaf(w0, B.w, cg0);  cg1 = fmaf(w1, B.w, cg1);
                    cb0 = fmaf(w0, cbv, cb0);  cb1 = fmaf(w1, cbv, cb1);
                    T0  = fmaf(-a0, T0, T0);
                    T1  = fmaf(-a1, T1, T1);
                }
            } else {
                i = ie;
            }
            if (__all_sync(0xffffffffu, (T0 < 1e-4f) & (T1 < 1e-4f))) i = n;
        }
        __syncwarp();
    }

    float b0 = bgp[0], b1 = bgp[1], b2 = bgp[2];
    cr0 = fminf(fmaxf(fmaf(T0, b0, cr0), 0.0f), 1.0f);
    cg0 = fminf(fmaxf(fmaf(T0, b1, cg0), 0.0f), 1.0f);
    cb0 = fminf(fmaxf(fmaf(T0, b2, cb0), 0.0f), 1.0f);
    cr1 = fminf(fmaxf(fmaf(T1, b0, cr1), 0.0f), 1.0f);
    cg1 = fminf(fmaxf(fmaf(T1, b1, cg1), 0.0f), 1.0f);
    cb1 = fminf(fmaxf(fmaf(T1, b2, cb1), 0.0f), 1.0f);

    int x  = tx8*8 + col;
    int y0 = ty8*8 + row;
    int o0 = (y0*WW + x) * 3;
    int o1 = ((y0 + 4)*WW + x) * 3;
    out[o0+0] = cr0; out[o0+1] = cg0; out[o0+2] = cb0;
    out[o1+0] = cr1; out[o1+1] = cg1; out[o1+2] = cb1;
}

// ---------------------------------------------------------------------------
extern "C" void kernel_launch(void* const* d_in, const int* in_sizes, int n_in,
                              void* d_out, int out_size)
{
    const float* ctrl  = (const float*)d_in[0];
    const float* fdc   = (const float*)d_in[1];
    const float* chol  = (const float*)d_in[2];
    const float* opac  = (const float*)d_in[3];
    const float* depth = (const float*)d_in[4];
    const float* bg    = (const float*)d_in[5];
    float* out = (float*)d_out;

    void* maskPtr = nullptr;
    cudaGetSymbolAddress(&maskPtr, d_mask);
    cudaMemsetAsync(maskPtr, 0, NTILE*MASKW*sizeof(uint32_t), 0);

    k_build<<<128, 128>>>(ctrl, fdc, chol, opac, depth);
    k_render<<<NTILE, 32>>>(bg, out);
}

// round 7
// speedup vs baseline: 1.2763x; 1.2763x over previous
#include <cuda_runtime.h>
#include <cstdint>

#define HH 256
#define WW 256
#define NUM_CURVES 256
#define GPER 64                            /* 2 beziers * 32 samples */
#define NGAUSS (NUM_CURVES*GPER)           /* 16384 */
#define LOG2E 1.4426950408889634f
#define NTILE 1024                         /* 32 x 32 tiles of 8x8 px */
#define MASKW (NGAUSS/32)                  /* 512 words per tile */
#define NSEG 4
#define SEGW (MASKW/NSEG)                  /* 128 words per segment */
#define CAP 512                            /* staged survivors per chunk */
#define CUT 14.0f                          /* cutoff: a >= exp(-14) ~ 8.3e-7 */

// ---- static scratch ----
__device__ float4   d_gA[NGAUSS];            // mx, my, c0p, c1p
__device__ float4   d_gB[NGAUSS];            // c2p, log2(alpha), cr, cg
__device__ float    d_gCb[NGAUSS];           // cb
__device__ uint32_t d_mask[NTILE*MASKW];     // per-tile visibility bitmask
__device__ float4   d_part[NSEG*NTILE*64];   // per (seg,tile,px): rgb, T

// ---------------------------------------------------------------------------
// K1 (fused prep + bezier + mask scatter): 128 blocks x 128 threads.
// ---------------------------------------------------------------------------
__global__ void __launch_bounds__(128)
k_build(const float* __restrict__ ctrl,
        const float* __restrict__ fdc,
        const float* __restrict__ chol,
        const float* __restrict__ opac,
        const float* __restrict__ depth)
{
    __shared__ float  sd[NUM_CURVES];
    __shared__ int    srank[2];
    __shared__ float4 sConic[2];
    __shared__ float4 sColEx[2];
    __shared__ float  sEy[2];

    int t   = threadIdx.x;
    int grp = t >> 6;
    int li  = t & 63;
    int ci  = blockIdx.x * 2 + grp;

    sd[t]       = depth[t];
    sd[t + 128] = depth[t + 128];
    if (t < 2) srank[t] = 0;
    __syncthreads();

    {   // stable rank of curve ci
        float d = sd[ci];
        int partial = 0;
        #pragma unroll
        for (int jj = 0; jj < 4; ++jj) {
            int j = li * 4 + jj;
            float dj = sd[j];
            partial += (dj < d) || (dj == d && j < ci);
        }
        partial += __shfl_xor_sync(0xffffffffu, partial, 16);
        partial += __shfl_xor_sync(0xffffffffu, partial, 8);
        partial += __shfl_xor_sync(0xffffffffu, partial, 4);
        partial += __shfl_xor_sync(0xffffffffu, partial, 2);
        partial += __shfl_xor_sync(0xffffffffu, partial, 1);
        if ((t & 31) == 0) atomicAdd(&srank[grp], partial);
    }

    if (t < 2) {
        int c = blockIdx.x * 2 + t;
        float c0 = chol[3*c+0] + 0.5f;
        float c1 = chol[3*c+1];
        float c2 = chol[3*c+2] + 0.5f;
        float s00 = c0*c0;
        float s01 = c0*c1;
        float s11 = c1*c1 + c2*c2;
        float inv = 1.0f / (s00*s11 - s01*s01);
        float A =  s11*inv;
        float B = -s01*inv;
        float C =  s00*inv;

        float al  = 1.0f / (1.0f + expf(-opac[c]));
        float l2a = log2f(al);
        float Q = fmaxf(2.0f * (CUT + logf(al)), 0.0f);
        float ex = sqrtf(Q * s00);
        float ey = sqrtf(Q * s11);

        sConic[t] = make_float4(-0.5f*LOG2E*A, -LOG2E*B, -0.5f*LOG2E*C, l2a);
        sColEx[t] = make_float4(1.0f/(1.0f+expf(-fdc[3*c+0])),
                                1.0f/(1.0f+expf(-fdc[3*c+1])),
                                1.0f/(1.0f+expf(-fdc[3*c+2])), ex);
        sEy[t] = ey;
    }
    __syncthreads();

    int k = li >> 5;
    int s = li & 31;
    float tt = 0.007f + (float)s * (0.986f / 31.0f);
    float u  = 1.0f - tt;
    float t2 = tt*tt, t3 = t2*tt, t4 = t2*t2, t5 = t4*tt;
    float u2 = u*u,   u3 = u2*u,  u4 = u2*u2, u5 = u4*u;
    float w0 = u5, w1 = 5.0f*tt*u4, w2 = 10.0f*t2*u3;
    float w3 = 10.0f*t3*u2, w4 = 5.0f*t4*u, w5 = t5;

    const float* cb_ = ctrl + ci * 20;
    int i0 = k*5;
    int a0=i0, a1=i0+1, a2=i0+2, a3=i0+3, a4=i0+4, a5=(i0+5)%10;
    float px = w0*cb_[a0*2]   + w1*cb_[a1*2]   + w2*cb_[a2*2]
             + w3*cb_[a3*2]   + w4*cb_[a4*2]   + w5*cb_[a5*2];
    float py = w0*cb_[a0*2+1] + w1*cb_[a1*2+1] + w2*cb_[a2*2+1]
             + w3*cb_[a3*2+1] + w4*cb_[a4*2+1] + w5*cb_[a5*2+1];
    float mx = (tanhf(px)*0.5f + 0.5f) * (float)WW;
    float my = (tanhf(py)*0.5f + 0.5f) * (float)HH;

    float4 cc = sConic[grp];
    float4 ce = sColEx[grp];
    float  ey = sEy[grp];
    int slot  = srank[grp] * 64 + li;

    d_gA[slot]  = make_float4(mx, my, cc.x, cc.y);
    d_gB[slot]  = make_float4(cc.z, cc.w, ce.x, ce.y);
    d_gCb[slot] = ce.z;

    float ex = ce.w;
    int xlo = max(0,  (int)ceilf ((mx - ex - 8.0f) * 0.125f - 1e-4f));
    int xhi = min(31, (int)floorf((mx + ex)        * 0.125f + 1e-4f));
    int ylo = max(0,  (int)ceilf ((my - ey - 8.0f) * 0.125f - 1e-4f));
    int yhi = min(31, (int)floorf((my + ey)        * 0.125f + 1e-4f));
    if (xlo <= xhi && ylo <= yhi) {
        uint32_t bit  = 1u << (slot & 31);
        int      word = slot >> 5;
        for (int ty = ylo; ty <= yhi; ++ty)
            for (int tx = xlo; tx <= xhi; ++tx)
                atomicOr(&d_mask[(ty*32 + tx)*MASKW + word], bit);
    }
}

// ---------------------------------------------------------------------------
// K2: depth-segmented per-tile compositing.
// grid = (1024 tiles, 4 segments), 64 threads (1 px each, 8x8 tile).
// Each block composites its 4096-slot depth range; emits (rgb, T) partial.
// ---------------------------------------------------------------------------
__global__ void __launch_bounds__(64)
k_render()
{
    __shared__ float4 shA[CAP];
    __shared__ float4 shB[CAP];
    __shared__ float  shCb[CAP];
    __shared__ int    sW[2];

    int t    = threadIdx.x;
    int lane = t & 31;
    int wid  = t >> 5;
    int tile = blockIdx.x;
    int seg  = blockIdx.y;
    int tx8  = tile & 31;
    int ty8  = tile >> 5;
    float px = (float)(tx8*8 + (t & 7)) + 0.5f;
    float py = (float)(ty8*8 + (t >> 3)) + 0.5f;

    // this thread owns 2 mask words of its segment (slots segBase + t*64 ..)
    const uint32_t* mw = d_mask + (size_t)tile*MASKW + seg*SEGW + t*2;
    uint32_t m0 = mw[0];
    uint32_t m1 = mw[1];
    int c = __popc(m0) + __popc(m1);

    // 64-thread exclusive scan
    int incl = c;
    #pragma unroll
    for (int d = 1; d < 32; d <<= 1) {
        int v = __shfl_up_sync(0xffffffffu, incl, d);
        if (lane >= d) incl += v;
    }
    if (lane == 31) sW[wid] = incl;
    __syncthreads();
    int w0s = sW[0];
    int total = w0s + sW[1];
    int off = (wid ? w0s : 0) + incl - c;

    float T = 1.0f, cr = 0.0f, cg = 0.0f, cb = 0.0f;
    int slotBase = seg*SEGW*32 + t*64;

    for (int base = 0; base < total; base += CAP) {
        if (base > 0 && __syncthreads_and(T < 1e-4f)) break;
        int lim = min(base + CAP, total);

        // gather my survivors that fall in [base, lim)
        if (off < lim && off + c > base) {
            int o = off;
            uint32_t mm = m0;
            int sb = slotBase;
            #pragma unroll
            for (int w = 0; w < 2; ++w) {
                while (mm) {
                    int b = __ffs(mm) - 1;
                    mm &= mm - 1;
                    if (o >= base && o < lim) {
                        int j = o - base;
                        int slot = sb + b;
                        shA[j]  = d_gA[slot];
                        shB[j]  = d_gB[slot];
                        shCb[j] = d_gCb[slot];
                    }
                    ++o;
                }
                mm = m1;
                sb = slotBase + 32;
            }
        }
        __syncthreads();

        int n = lim - base;
        int i = 0;
        while (i < n) {
            int ie = min(i + 64, n);
            if (T >= 1e-4f) {
                for (; i < ie; ++i) {
                    float4 A = shA[i];
                    float4 B = shB[i];
                    float dx = px - A.x;
                    float dy = py - A.y;
                    float e = B.y;                       // log2(alpha)
                    e = fmaf(A.z, dx*dx, e);
                    e = fmaf(A.w, dx*dy, e);
                    e = fmaf(B.x, dy*dy, e);
                    float a;
                    asm("ex2.approx.f32 %0, %1;" : "=f"(a) : "f"(e));
                    float w = a * T;
                    cr = fmaf(w, B.z, cr);
                    cg = fmaf(w, B.w, cg);
                    cb = fmaf(w, shCb[i], cb);
                    T  = fmaf(-a, T, T);
                }
            } else {
                i = ie;
            }
            if (__all_sync(0xffffffffu, T < 1e-4f)) i = n;
        }
        __syncthreads();
    }

    d_part[(seg*NTILE + tile)*64 + t] = make_float4(cr, cg, cb, T);
}

// ---------------------------------------------------------------------------
// K3: combine 4 segment partials per pixel, add background, clip, store.
// 1024 blocks x 64 threads (one per tile pixel).
// ---------------------------------------------------------------------------
__global__ void __launch_bounds__(64)
k_combine(const float* __restrict__ bgp, float* __restrict__ out)
{
    int t    = threadIdx.x;
    int tile = blockIdx.x;
    int tx8  = tile & 31;
    int ty8  = tile >> 5;

    float T = 1.0f, cr = 0.0f, cg = 0.0f, cb = 0.0f;
    #pragma unroll
    for (int s = 0; s < NSEG; ++s) {
        float4 p = d_part[(s*NTILE + tile)*64 + t];
        cr = fmaf(T, p.x, cr);
        cg = fmaf(T, p.y, cg);
        cb = fmaf(T, p.z, cb);
        T *= p.w;
    }

    float b0 = bgp[0], b1 = bgp[1], b2 = bgp[2];
    cr = fminf(fmaxf(fmaf(T, b0, cr), 0.0f), 1.0f);
    cg = fminf(fmaxf(fmaf(T, b1, cg), 0.0f), 1.0f);
    cb = fminf(fmaxf(fmaf(T, b2, cb), 0.0f), 1.0f);

    int x = tx8*8 + (t & 7);
    int y = ty8*8 + (t >> 3);
    int o = (y*WW + x) * 3;
    out[o+0] = cr;
    out[o+1] = cg;
    out[o+2] = cb;
}

// ---------------------------------------------------------------------------
extern "C" void kernel_launch(void* const* d_in, const int* in_sizes, int n_in,
                              void* d_out, int out_size)
{
    const float* ctrl  = (const float*)d_in[0];
    const float* fdc   = (const float*)d_in[1];
    const float* chol  = (const float*)d_in[2];
    const float* opac  = (const float*)d_in[3];
    const float* depth = (const float*)d_in[4];
    const float* bg    = (const float*)d_in[5];
    float* out = (float*)d_out;

    void* maskPtr = nullptr;
    cudaGetSymbolAddress(&maskPtr, d_mask);
    cudaMemsetAsync(maskPtr, 0, NTILE*MASKW*sizeof(uint32_t), 0);

    k_build<<<128, 128>>>(ctrl, fdc, chol, opac, depth);
    k_render<<<dim3(NTILE, NSEG), 64>>>();
    k_combine<<<NTILE, 64>>>(bg, out);
}